// round 4
// baseline (speedup 1.0000x reference)
#include <cuda_runtime.h>
#include <cuda_bf16.h>

// KOrderGPMap: B=32, L=64, C=4. x is one-hot => all einsums are gathers.
// phi[b] = th0 + sum_l th1[s_l] + sum_{l0<l1} th2[s0*256+s1]
//        + sum_{l0<l1<l2} th3[s0*65536+s1*256+s2],  s_l = 4*l + idx[b,l].

#define B 32
#define L 64
#define NTRIPLES 41664   // C(64,3)
#define NPAIRS   2016    // C(64,2)
#define NT 256
#define UNROLL 8
#define CHUNK (NT * UNROLL)            // 2048 triples per block
#define NCHUNKS ((NTRIPLES + CHUNK - 1) / CHUNK)   // 21

// Packed triple table: (l0<<12)|(l1<<6)|l2. Filled each launch (deterministic).
__device__ unsigned int d_tab[NTRIPLES];

__global__ void fill_tab_kernel(float* __restrict__ out) {
    // also zero the output (d_out is poisoned before timing)
    if (blockIdx.x == 0 && threadIdx.x < B) out[threadIdx.x] = 0.0f;

    int p = blockIdx.x * blockDim.x + threadIdx.x;
    if (p >= NPAIRS) return;
    // decode pair index p -> (l0, l1), pairs ordered by l0 asc then l1 asc
    int rem = p, l0 = 0;
    while (rem >= 63 - l0) { rem -= 63 - l0; l0++; }
    int l1 = l0 + 1 + rem;
    // flat offset of first triple for this (l0, l1)
    int n = 64 - l0;
    int base = NTRIPLES - n * (n - 1) * (n - 2) / 6;       // triples with first < l0
    int t1 = (62 - l0) * (63 - l0) / 2;                    // T(62-l0)
    int t2 = (63 - l1) * (64 - l1) / 2;                    // T(63-l1)
    int off = base + t1 - t2;
    unsigned int hi = ((unsigned)l0 << 12) | ((unsigned)l1 << 6);
    for (int l2 = l1 + 1; l2 < 64; ++l2) d_tab[off++] = hi | (unsigned)l2;
}

__global__ __launch_bounds__(NT)
void kgp2_kernel(const float* __restrict__ x,      // (B, 256)
                 const float* __restrict__ th0,    // (1,)
                 const float* __restrict__ th1,    // (256,)
                 const float* __restrict__ th2,    // (256*256,)
                 const float* __restrict__ th3,    // (256^3,)
                 float* __restrict__ out)          // (B,)
{
    const int b    = blockIdx.y;
    const int tid  = threadIdx.x;
    const int warp = tid >> 5;
    const int lane = tid & 31;

    __shared__ int s[L];
    __shared__ float wsum[NT / 32];

    // Decode one-hot: c = 0*x0 + 1*x1 + 2*x2 + 3*x3 (exact for one-hot).
    if (tid < L) {
        const float4 v = reinterpret_cast<const float4*>(x)[b * L + tid];
        int c = (int)(v.y + 2.0f * v.z + 3.0f * v.w + 0.5f);
        s[tid] = tid * 4 + c;
    }
    __syncthreads();

    float acc = 0.0f;

    if (blockIdx.x < NCHUNKS) {
        // Order-3 gathers: UNROLL independent loads per lane, consecutive
        // triples across lanes (coalesced table reads, shared theta3 rows).
        const int base = blockIdx.x * CHUNK + tid;
        #pragma unroll
        for (int k = 0; k < UNROLL; ++k) {
            const int idx = base + k * NT;
            if (idx < NTRIPLES) {
                const unsigned int tv = d_tab[idx];
                const int addr = (s[tv >> 12] << 16)
                               + (s[(tv >> 6) & 63] << 8)
                               +  s[tv & 63];
                acc += __ldg(&th3[addr]);
            }
        }
    } else {
        // Dedicated block per batch: order-2 + order-1 + theta_0.
        const int l0  = tid & 63;
        const int rep = tid >> 6;       // 0..3
        const int s0  = s[l0] << 8;
        for (int l1 = l0 + 1 + rep; l1 < L; l1 += 4)
            acc += __ldg(&th2[s0 + s[l1]]);
        if (tid < L) acc += __ldg(&th1[s[tid]]);
        if (tid == 0) acc += th0[0];
    }

    // Warp reduce, then block reduce, then one atomic per block.
    #pragma unroll
    for (int off = 16; off > 0; off >>= 1)
        acc += __shfl_xor_sync(0xffffffffu, acc, off);
    if (lane == 0) wsum[warp] = acc;
    __syncthreads();

    if (tid == 0) {
        float total = 0.0f;
        #pragma unroll
        for (int w = 0; w < NT / 32; ++w) total += wsum[w];
        atomicAdd(&out[b], total);
    }
}

extern "C" void kernel_launch(void* const* d_in, const int* in_sizes, int n_in,
                              void* d_out, int out_size) {
    const float* x   = (const float*)d_in[0];
    const float* th0 = (const float*)d_in[1];
    const float* th1 = (const float*)d_in[2];
    const float* th2 = (const float*)d_in[3];
    const float* th3 = (const float*)d_in[4];
    float* out = (float*)d_out;

    fill_tab_kernel<<<(NPAIRS + NT - 1) / NT, NT>>>(out);
    dim3 grid(NCHUNKS + 1, B);
    kgp2_kernel<<<grid, NT>>>(x, th0, th1, th2, th3, out);
}

// round 6
// speedup vs baseline: 1.1376x; 1.1376x over previous
#include <cuda_runtime.h>
#include <cuda_bf16.h>

// KOrderGPMap: B=32, L=64, C=4. x is one-hot => all einsums are gathers.
// phi[b] = th0 + sum_l th1[s_l] + sum_{l0<l1} th2[s0*256+s1]
//        + sum_{l0<l1<l2} th3[s0*65536+s1*256+s2],  s_l = 4*l + idx[b,l].
//
// Decomposition by MIDDLE index l1: for fixed l1 the (l0,l2) set is a
// rectangle [0,l1) x (l1,63], size l1*(63-l1) <= 992. No lookup table.

#define B 32
#define L 64
#define NT 128
#define MAXK 8   // ceil(992 / 128)

__global__ void zero_out_kernel(float* __restrict__ out) {
    if (threadIdx.x < B) out[threadIdx.x] = 0.0f;
}

__global__ __launch_bounds__(NT)
void kgp3_kernel(const float* __restrict__ x,      // (B, 256)
                 const float* __restrict__ th0,    // (1,)
                 const float* __restrict__ th1,    // (256,)
                 const float* __restrict__ th2,    // (256*256,)
                 const float* __restrict__ th3,    // (256^3,)
                 float* __restrict__ out)          // (B,)
{
    const int l1   = blockIdx.x;   // 0..63  (middle index of the triple)
    const int b    = blockIdx.y;   // 0..31
    const int tid  = threadIdx.x;
    const int warp = tid >> 5;
    const int lane = tid & 31;

    __shared__ int s[L];
    __shared__ float wsum[NT / 32];

    // Decode one-hot: c = 0*x0 + 1*x1 + 2*x2 + 3*x3 (exact for one-hot).
    if (tid < L) {
        const float4 v = reinterpret_cast<const float4*>(x)[b * L + tid];
        int c = (int)(v.y + 2.0f * v.z + 3.0f * v.w + 0.5f);
        s[tid] = tid * 4 + c;
    }
    __syncthreads();

    const int w      = 63 - l1;        // number of l2 values
    const int cnt    = l1 * w;         // rectangle size, <= 992
    const int s1part = s[l1] << 8;
    // Exact magic reciprocal for division by w (w in [1,63], j <= 991).
    const unsigned long long mult =
        w ? (0x100000000ull + (unsigned)w - 1) / (unsigned)w : 0ull;

    float acc = 0.0f;

    // Order-3: compute all 8 addresses first (LDS + ALU), then issue 8
    // independent predicated LDGs back-to-back for maximum MLP.
    int addr[MAXK];
    bool act[MAXK];
    #pragma unroll
    for (int k = 0; k < MAXK; ++k) {
        const int j = tid + k * NT;
        act[k] = (j < cnt);
        const int l0 = (int)(((unsigned long long)(unsigned)j * mult) >> 32);
        const int l2 = l1 + 1 + (j - l0 * w);
        // clamp to safe indices when inactive (loads are predicated off anyway)
        addr[k] = act[k] ? ((s[l0] << 16) + s1part + s[l2]) : 0;
    }
    #pragma unroll
    for (int k = 0; k < MAXK; ++k) {
        if (act[k]) acc += __ldg(&th3[addr[k]]);
    }

    // Order-2: pairs (l0, l1) with l0 < l1 — one per thread.
    if (tid < l1) acc += __ldg(&th2[(s[tid] << 8) + s[l1]]);

    // Order-1 + theta_0: block l1 == 0 (which has no order-3/order-2 work).
    if (l1 == 0 && tid < L) {
        acc += __ldg(&th1[s[tid]]);
        if (tid == 0) acc += th0[0];
    }

    // Warp reduce, block reduce, one atomic per block.
    #pragma unroll
    for (int off = 16; off > 0; off >>= 1)
        acc += __shfl_xor_sync(0xffffffffu, acc, off);
    if (lane == 0) wsum[warp] = acc;
    __syncthreads();

    if (tid == 0) {
        float total = 0.0f;
        #pragma unroll
        for (int wi = 0; wi < NT / 32; ++wi) total += wsum[wi];
        atomicAdd(&out[b], total);
    }
}

extern "C" void kernel_launch(void* const* d_in, const int* in_sizes, int n_in,
                              void* d_out, int out_size) {
    const float* x   = (const float*)d_in[0];
    const float* th0 = (const float*)d_in[1];
    const float* th1 = (const float*)d_in[2];
    const float* th2 = (const float*)d_in[3];
    const float* th3 = (const float*)d_in[4];
    float* out = (float*)d_out;

    zero_out_kernel<<<1, 32>>>(out);
    dim3 grid(L, B);
    kgp3_kernel<<<grid, NT>>>(x, th0, th1, th2, th3, out);
}

// round 7
// speedup vs baseline: 1.3988x; 1.2296x over previous
#include <cuda_runtime.h>
#include <cuda_bf16.h>

// KOrderGPMap: B=32, L=64, C=4. x one-hot => gathers, s_l = 4*l + idx[b,l].
// phi[b] = th0 + sum th1[s_l] + sum_{l0<l1} th2[s0*256+s1]
//        + sum_{l0<l1<l2} th3[s0*65536+s1*256+s2].
//
// Block (l1, b). For each l0 < l1 the needed theta3 elements live in the
// CONTIGUOUS suffix th3[s0,s1, 4*(l1+1) .. 255]: lane <-> l2, float4 loads,
// component selected by c2 = s[l2]&3 (fixed per lane per block).

#define B 32
#define L 64
#define NT 128

__global__ void zero_out_kernel(float* __restrict__ out) {
    if (threadIdx.x < B) out[threadIdx.x] = 0.0f;
}

__device__ __forceinline__ float pick(float4 v, int c) {
    float lo = (c & 1) ? v.y : v.x;
    float hi = (c & 1) ? v.w : v.z;
    return (c & 2) ? hi : lo;
}

__global__ __launch_bounds__(NT)
void kgp4_kernel(const float* __restrict__ x,      // (B, 256)
                 const float* __restrict__ th0,    // (1,)
                 const float* __restrict__ th1,    // (256,)
                 const float* __restrict__ th2,    // (256*256,)
                 const float* __restrict__ th3,    // (256^3,)
                 float* __restrict__ out)          // (B,)
{
    const int l1   = blockIdx.x;   // middle index, 0..63
    const int b    = blockIdx.y;   // 0..31
    const int tid  = threadIdx.x;
    const int warp = tid >> 5;
    const int lane = tid & 31;

    __shared__ int s[L];
    __shared__ float wsum[NT / 32];

    if (tid < L) {
        const float4 v = reinterpret_cast<const float4*>(x)[b * L + tid];
        int c = (int)(v.y + 2.0f * v.z + 3.0f * v.w + 0.5f);
        s[tid] = tid * 4 + c;
    }
    __syncthreads();

    // Per-lane suffix slots (constant across the l0 loop):
    const int  l2a = l1 + 1 + lane;        // strip A: lanes cover l2 in (l1, l1+32]
    const int  l2b = l2a + 32;             // strip B: (l1+32, l1+64]
    const bool va  = (l2a < L);
    const bool vb  = (l2b < L);
    const int  c2a = va ? (s[l2a] & 3) : 0;
    const int  c2b = vb ? (s[l2b] & 3) : 0;

    const float4* __restrict__ t3v = reinterpret_cast<const float4*>(th3);
    const int rowoff = s[l1] << 6;         // s1*256 floats = s1*64 float4s

    float acc = 0.0f;

    // Warps stride over l0; 2x unroll for MLP (up to 4 LDG.128 in flight).
    #pragma unroll 2
    for (int l0 = warp; l0 < l1; l0 += NT / 32) {
        const int base4 = (s[l0] << 14) + rowoff;   // float4 index of row start
        if (va) acc += pick(__ldg(&t3v[base4 + l2a]), c2a);
        if (vb) acc += pick(__ldg(&t3v[base4 + l2b]), c2b);
    }

    // Order-2: pairs (l0, l1), one per thread.
    if (tid < l1) acc += __ldg(&th2[(s[tid] << 8) + s[l1]]);

    // Order-1 + theta_0: block l1 == 0 (no order-2/3 work there).
    if (l1 == 0 && tid < L) {
        acc += __ldg(&th1[s[tid]]);
        if (tid == 0) acc += th0[0];
    }

    #pragma unroll
    for (int off = 16; off > 0; off >>= 1)
        acc += __shfl_xor_sync(0xffffffffu, acc, off);
    if (lane == 0) wsum[warp] = acc;
    __syncthreads();

    if (tid == 0) {
        float total = 0.0f;
        #pragma unroll
        for (int wi = 0; wi < NT / 32; ++wi) total += wsum[wi];
        atomicAdd(&out[b], total);
    }
}

extern "C" void kernel_launch(void* const* d_in, const int* in_sizes, int n_in,
                              void* d_out, int out_size) {
    const float* x   = (const float*)d_in[0];
    const float* th0 = (const float*)d_in[1];
    const float* th1 = (const float*)d_in[2];
    const float* th2 = (const float*)d_in[3];
    const float* th3 = (const float*)d_in[4];
    float* out = (float*)d_out;

    zero_out_kernel<<<1, 32>>>(out);
    dim3 grid(L, B);
    kgp4_kernel<<<grid, NT>>>(x, th0, th1, th2, th3, out);
}